// round 6
// baseline (speedup 1.0000x reference)
#include <cuda_runtime.h>

// ---------------------------------------------------------------------------
// Tree3 fused, round 6: R5 datapath + 640 threads / 102-reg cap -> 20 warps/SM
// (was 16). Packed f32x2 everywhere, two-subpass conv, conflict-free pools.
// ---------------------------------------------------------------------------

#define THREADS 640
#define BTOT 2048
#define NPAIR 2                    // image pairs per CTA (4 images)

// float2-unit strides
#define IMG_ROW_F2   34
#define IMG_PLANE_F2 1092
#define POOL_ROW_F2  15
#define POOL_CH_F2   211

#define SZ_IMG_F2    (NPAIR*3*IMG_PLANE_F2)
#define SZ_POOL_F2   (NPAIR*45*POOL_CH_F2)
#define OFF_POOL_F2  SZ_IMG_F2
#define OFF_W        (2*(SZ_IMG_F2 + SZ_POOL_F2))
#define OFF_CB       (OFF_W + 1128)
#define OFF_T        (OFF_CB + 48)
#define SMEM_FLOATS  (OFF_T + 4*336)

__device__ __forceinline__ float2 ffma2(float2 a, float2 b, float2 c) {
    unsigned long long au = *reinterpret_cast<unsigned long long*>(&a);
    unsigned long long bu = *reinterpret_cast<unsigned long long*>(&b);
    unsigned long long cu = *reinterpret_cast<unsigned long long*>(&c);
    unsigned long long du;
    asm("fma.rn.f32x2 %0, %1, %2, %3;" : "=l"(du) : "l"(au), "l"(bu), "l"(cu));
    return *reinterpret_cast<float2*>(&du);
}

__device__ __forceinline__ float sigmoidf_fast(float v) {
    return __fdividef(1.0f, 1.0f + __expf(-v));
}

// One column-subpass of the 5x5 conv over an image pair:
// NC conv columns x 2 conv rows -> NC/2 pooled pre-activations.
template<int NC>
__device__ __forceinline__ void conv_subpass(const float2* __restrict__ ib,
                                             const float*  __restrict__ wb,
                                             float2* __restrict__ pmax)
{
    constexpr int NF4 = (NC + 5) / 2;
    float2 acc0[NC], acc1[NC];
    #pragma unroll
    for (int k = 0; k < NC; k++) {
        acc0[k] = make_float2(0.f, 0.f);
        acc1[k] = make_float2(0.f, 0.f);
    }

    float2 wpk[5];
    #pragma unroll
    for (int r = 0; r < 6; r++) {
        float2 P[2 * NF4];
        const float4* rp = (const float4*)(ib + r * IMG_ROW_F2);
        #pragma unroll
        for (int u = 0; u < NF4; u++) {
            float4 q = rp[u];
            P[2*u]   = make_float2(q.x, q.y);
            P[2*u+1] = make_float2(q.z, q.w);
        }
        if (r > 0) {
            #pragma unroll
            for (int kx = 0; kx < 5; kx++)
                #pragma unroll
                for (int ox = 0; ox < NC; ox++)
                    acc1[ox] = ffma2(P[ox + kx], wpk[kx], acc1[ox]);
        }
        if (r < 5) {
            #pragma unroll
            for (int kx = 0; kx < 5; kx++) {
                float w = wb[r * 5 + kx];
                wpk[kx] = make_float2(w, w);
            }
            #pragma unroll
            for (int kx = 0; kx < 5; kx++)
                #pragma unroll
                for (int ox = 0; ox < NC; ox++)
                    acc0[ox] = ffma2(P[ox + kx], wpk[kx], acc0[ox]);
        }
    }

    #pragma unroll
    for (int pj = 0; pj < NC / 2; pj++) {
        float vx = fmaxf(fmaxf(acc0[2*pj].x, acc0[2*pj+1].x),
                         fmaxf(acc1[2*pj].x, acc1[2*pj+1].x));
        float vy = fmaxf(fmaxf(acc0[2*pj].y, acc0[2*pj+1].y),
                         fmaxf(acc1[2*pj].y, acc1[2*pj+1].y));
        pmax[pj] = make_float2(vx, vy);
    }
}

__global__ __launch_bounds__(THREADS, 1)
void tree3_fused(const float* __restrict__ x,
                 const float* __restrict__ conv_w,
                 const float* __restrict__ conv_b,
                 const float* __restrict__ tree_w,
                 const float* __restrict__ tree_b,
                 const float* __restrict__ fc_w,
                 const float* __restrict__ fc_b,
                 float* __restrict__ out)
{
    extern __shared__ __align__(16) float sm[];
    float2* s_img  = reinterpret_cast<float2*>(sm);
    float2* s_pool = reinterpret_cast<float2*>(sm) + OFF_POOL_F2;
    float*  s_w    = sm + OFF_W;
    float*  s_cb   = sm + OFF_CB;
    float*  s_t    = sm + OFF_T;

    const int tid = threadIdx.x;
    const int b0  = blockIdx.x * (2 * NPAIR);

    // ---- stage conv weights + bias ----
    for (int idx = tid; idx < 1125; idx += THREADS) s_w[idx] = conv_w[idx];
    if (tid < 45) s_cb[tid] = conv_b[tid];

    // ---- stage images pairwise-interleaved (float4 in/out) ----
    for (int idx = tid; idx < NPAIR * 3 * 32 * 8; idx += THREADS) {
        int grp  = idx & 7;
        int row  = (idx >> 3) & 31;
        int gch  = (idx >> 8) % 3;
        int pair = idx / (3 * 32 * 8);
        const float* pA = x + (size_t)(b0 + 2 * pair) * 3072
                            + gch * 1024 + row * 32 + grp * 4;
        float4 a = *(const float4*)pA;
        float4 b = *(const float4*)(pA + 3072);
        float4* dst = (float4*)(s_img + (pair * 3 + gch) * IMG_PLANE_F2
                                      + row * IMG_ROW_F2 + grp * 4);
        dst[0] = make_float4(a.x, b.x, a.y, b.y);
        dst[1] = make_float4(a.z, b.z, a.w, b.w);
    }
    __syncthreads();

    // ---- phase 1: packed conv + sigmoid(max-pool), two column subpasses ----
    for (int task = tid; task < NPAIR * 45 * 28; task += THREADS) {
        int c    = task % 45;
        int rest = task / 45;
        int half = rest & 1;
        int pi   = (rest >> 1) % 14;
        int pair = rest / 28;

        int g  = c / 15;
        const float*  wb = s_w + c * 25;
        const float2* ib = s_img + (pair * 3 + g) * IMG_PLANE_F2
                                 + (pi * 2) * IMG_ROW_F2 + half * 14;

        float2 pmax[7];
        conv_subpass<8>(ib,     wb, pmax);
        conv_subpass<6>(ib + 8, wb, pmax + 4);

        float bias = s_cb[c];
        float2* pb = s_pool + (pair * 45 + c) * POOL_CH_F2
                            + pi * POOL_ROW_F2 + half * 7;
        #pragma unroll
        for (int pj = 0; pj < 7; pj++)
            pb[pj] = make_float2(sigmoidf_fast(pmax[pj].x + bias),
                                 sigmoidf_fast(pmax[pj].y + bias));
    }
    __syncthreads();

    // ---- phase 2: tree einsum, 4 accumulator chains per pair ----
    if (tid < 336) {
        int f   = tid / 21;
        int r21 = tid % 21;
        int g   = r21 / 7;
        int i   = r21 % 7;

        const float4* wp = (const float4*)tree_w + (f * 2205 + g * 49 + i * 7);

        float2 aA[NPAIR], aB[NPAIR], aC[NPAIR], aD[NPAIR];
        #pragma unroll
        for (int p = 0; p < NPAIR; p++) {
            aA[p] = make_float2(0.f, 0.f); aB[p] = make_float2(0.f, 0.f);
            aC[p] = make_float2(0.f, 0.f); aD[p] = make_float2(0.f, 0.f);
        }

        #pragma unroll 3
        for (int m = 0; m < 15; m++) {
            const float4* wm = wp + m * 147;
            int ch = g * 15 + m;
            #pragma unroll
            for (int j = 0; j < 7; j++) {
                float4 w = wm[j];
                #pragma unroll
                for (int p = 0; p < NPAIR; p++) {
                    const float2* pp = s_pool + (p * 45 + ch) * POOL_CH_F2
                                              + (2 * i) * POOL_ROW_F2 + 2 * j;
                    aA[p] = ffma2(pp[0],                make_float2(w.x, w.x), aA[p]);
                    aB[p] = ffma2(pp[1],                make_float2(w.y, w.y), aB[p]);
                    aC[p] = ffma2(pp[POOL_ROW_F2],      make_float2(w.z, w.z), aC[p]);
                    aD[p] = ffma2(pp[POOL_ROW_F2 + 1],  make_float2(w.w, w.w), aD[p]);
                }
            }
        }

        float tb = tree_b[tid];
        #pragma unroll
        for (int p = 0; p < NPAIR; p++) {
            float sx = (aA[p].x + aB[p].x) + (aC[p].x + aD[p].x);
            float sy = (aA[p].y + aB[p].y) + (aC[p].y + aD[p].y);
            s_t[(2*p    ) * 336 + tid] = sigmoidf_fast(sx + tb);
            s_t[(2*p + 1) * 336 + tid] = sigmoidf_fast(sy + tb);
        }
    }
    __syncthreads();

    // ---- phase 3: FC 336 -> 10 ----
    if (tid < 320) {
        int part  = tid & 7;
        int combo = tid >> 3;
        int img   = combo / 10;
        int o     = combo % 10;
        const float* tv = s_t + img * 336;
        const float* wv = fc_w + o * 336;
        float s = 0.f;
        for (int k = part; k < 336; k += 8)
            s = fmaf(tv[k], wv[k], s);
        s += __shfl_xor_sync(0xffffffffu, s, 1);
        s += __shfl_xor_sync(0xffffffffu, s, 2);
        s += __shfl_xor_sync(0xffffffffu, s, 4);
        if (part == 0)
            out[(b0 + img) * 10 + o] = s + fc_b[o];
    }
}

extern "C" void kernel_launch(void* const* d_in, const int* in_sizes, int n_in,
                              void* d_out, int out_size)
{
    const float* x      = (const float*)d_in[0];
    const float* conv_w = (const float*)d_in[1];
    const float* conv_b = (const float*)d_in[2];
    const float* tree_w = (const float*)d_in[3];
    const float* tree_b = (const float*)d_in[4];
    const float* fc_w   = (const float*)d_in[5];
    const float* fc_b   = (const float*)d_in[6];
    float* out = (float*)d_out;

    const int smem_bytes = SMEM_FLOATS * (int)sizeof(float);
    cudaFuncSetAttribute(tree3_fused,
                         cudaFuncAttributeMaxDynamicSharedMemorySize, smem_bytes);

    tree3_fused<<<BTOT / (2 * NPAIR), THREADS, smem_bytes>>>(
        x, conv_w, conv_b, tree_w, tree_b, fc_w, fc_b, out);
}

// round 7
// speedup vs baseline: 1.1988x; 1.1988x over previous
#include <cuda_runtime.h>

// ---------------------------------------------------------------------------
// Tree3 fused, round 7: conv phase identical to R5 (best). Tree phase
// restructured: warp-lane layout (gi major) makes pool LDS broadcast across
// the 16 f-lanes, m is split across lane pairs (672 tasks, shfl combine).
// ---------------------------------------------------------------------------

#define THREADS 512
#define BTOT 2048
#define NPAIR 2                    // image pairs per CTA (4 images)

// float2-unit strides
#define IMG_ROW_F2   34
#define IMG_PLANE_F2 1092
#define POOL_ROW_F2  15
#define POOL_CH_F2   211

#define SZ_IMG_F2    (NPAIR*3*IMG_PLANE_F2)
#define SZ_POOL_F2   (NPAIR*45*POOL_CH_F2)
#define OFF_POOL_F2  SZ_IMG_F2
#define OFF_W        (2*(SZ_IMG_F2 + SZ_POOL_F2))
#define OFF_CB       (OFF_W + 1128)
#define OFF_T        (OFF_CB + 48)
#define SMEM_FLOATS  (OFF_T + 4*336)

__device__ __forceinline__ float2 ffma2(float2 a, float2 b, float2 c) {
    unsigned long long au = *reinterpret_cast<unsigned long long*>(&a);
    unsigned long long bu = *reinterpret_cast<unsigned long long*>(&b);
    unsigned long long cu = *reinterpret_cast<unsigned long long*>(&c);
    unsigned long long du;
    asm("fma.rn.f32x2 %0, %1, %2, %3;" : "=l"(du) : "l"(au), "l"(bu), "l"(cu));
    return *reinterpret_cast<float2*>(&du);
}

__device__ __forceinline__ float sigmoidf_fast(float v) {
    return __fdividef(1.0f, 1.0f + __expf(-v));
}

// One column-subpass of the 5x5 conv over an image pair (unchanged from R5)
template<int NC>
__device__ __forceinline__ void conv_subpass(const float2* __restrict__ ib,
                                             const float*  __restrict__ wb,
                                             float2* __restrict__ pmax)
{
    constexpr int NF4 = (NC + 5) / 2;
    float2 acc0[NC], acc1[NC];
    #pragma unroll
    for (int k = 0; k < NC; k++) {
        acc0[k] = make_float2(0.f, 0.f);
        acc1[k] = make_float2(0.f, 0.f);
    }

    float2 wpk[5];
    #pragma unroll
    for (int r = 0; r < 6; r++) {
        float2 P[2 * NF4];
        const float4* rp = (const float4*)(ib + r * IMG_ROW_F2);
        #pragma unroll
        for (int u = 0; u < NF4; u++) {
            float4 q = rp[u];
            P[2*u]   = make_float2(q.x, q.y);
            P[2*u+1] = make_float2(q.z, q.w);
        }
        if (r > 0) {
            #pragma unroll
            for (int kx = 0; kx < 5; kx++)
                #pragma unroll
                for (int ox = 0; ox < NC; ox++)
                    acc1[ox] = ffma2(P[ox + kx], wpk[kx], acc1[ox]);
        }
        if (r < 5) {
            #pragma unroll
            for (int kx = 0; kx < 5; kx++) {
                float w = wb[r * 5 + kx];
                wpk[kx] = make_float2(w, w);
            }
            #pragma unroll
            for (int kx = 0; kx < 5; kx++)
                #pragma unroll
                for (int ox = 0; ox < NC; ox++)
                    acc0[ox] = ffma2(P[ox + kx], wpk[kx], acc0[ox]);
        }
    }

    #pragma unroll
    for (int pj = 0; pj < NC / 2; pj++) {
        float vx = fmaxf(fmaxf(acc0[2*pj].x, acc0[2*pj+1].x),
                         fmaxf(acc1[2*pj].x, acc1[2*pj+1].x));
        float vy = fmaxf(fmaxf(acc0[2*pj].y, acc0[2*pj+1].y),
                         fmaxf(acc1[2*pj].y, acc1[2*pj+1].y));
        pmax[pj] = make_float2(vx, vy);
    }
}

__global__ __launch_bounds__(THREADS, 1)
void tree3_fused(const float* __restrict__ x,
                 const float* __restrict__ conv_w,
                 const float* __restrict__ conv_b,
                 const float* __restrict__ tree_w,
                 const float* __restrict__ tree_b,
                 const float* __restrict__ fc_w,
                 const float* __restrict__ fc_b,
                 float* __restrict__ out)
{
    extern __shared__ __align__(16) float sm[];
    float2* s_img  = reinterpret_cast<float2*>(sm);
    float2* s_pool = reinterpret_cast<float2*>(sm) + OFF_POOL_F2;
    float*  s_w    = sm + OFF_W;
    float*  s_cb   = sm + OFF_CB;
    float*  s_t    = sm + OFF_T;

    const int tid = threadIdx.x;
    const int b0  = blockIdx.x * (2 * NPAIR);

    // ---- stage conv weights + bias ----
    for (int idx = tid; idx < 1125; idx += THREADS) s_w[idx] = conv_w[idx];
    if (tid < 45) s_cb[tid] = conv_b[tid];

    // ---- stage images pairwise-interleaved (float4 in/out) ----
    for (int idx = tid; idx < NPAIR * 3 * 32 * 8; idx += THREADS) {
        int grp  = idx & 7;
        int row  = (idx >> 3) & 31;
        int gch  = (idx >> 8) % 3;
        int pair = idx / (3 * 32 * 8);
        const float* pA = x + (size_t)(b0 + 2 * pair) * 3072
                            + gch * 1024 + row * 32 + grp * 4;
        float4 a = *(const float4*)pA;
        float4 b = *(const float4*)(pA + 3072);
        float4* dst = (float4*)(s_img + (pair * 3 + gch) * IMG_PLANE_F2
                                      + row * IMG_ROW_F2 + grp * 4);
        dst[0] = make_float4(a.x, b.x, a.y, b.y);
        dst[1] = make_float4(a.z, b.z, a.w, b.w);
    }
    __syncthreads();

    // ---- phase 1: packed conv + sigmoid(max-pool) (unchanged) ----
    for (int task = tid; task < NPAIR * 45 * 28; task += THREADS) {
        int c    = task % 45;
        int rest = task / 45;
        int half = rest & 1;
        int pi   = (rest >> 1) % 14;
        int pair = rest / 28;

        int g  = c / 15;
        const float*  wb = s_w + c * 25;
        const float2* ib = s_img + (pair * 3 + g) * IMG_PLANE_F2
                                 + (pi * 2) * IMG_ROW_F2 + half * 14;

        float2 pmax[7];
        conv_subpass<8>(ib,     wb, pmax);
        conv_subpass<6>(ib + 8, wb, pmax + 4);

        float bias = s_cb[c];
        float2* pb = s_pool + (pair * 45 + c) * POOL_CH_F2
                            + pi * POOL_ROW_F2 + half * 7;
        #pragma unroll
        for (int pj = 0; pj < 7; pj++)
            pb[pj] = make_float2(sigmoidf_fast(pmax[pj].x + bias),
                                 sigmoidf_fast(pmax[pj].y + bias));
    }
    __syncthreads();

    // ---- phase 2: tree einsum, gi-major lanes (pool LDS broadcasts), ----
    // ---- m split across lane pairs, shfl_xor(1) combine.             ----
    for (int t = tid; t < 21 * 32; t += THREADS) {
        int gi  = t >> 5;            // 0..20 : same for all lanes of a warp
        int sub = t & 31;
        int f   = sub >> 1;          // 0..15
        int mh  = sub & 1;           // m-half
        int g   = gi / 7;
        int i   = gi % 7;

        int m0 = mh ? 8 : 0;
        int m1 = mh ? 15 : 8;

        const float4* wp = (const float4*)tree_w + (f * 2205 + g * 49 + i * 7);

        float2 a0 = make_float2(0.f, 0.f), a1 = a0;   // pair 0: row 2i / 2i+1
        float2 c0 = a0, c1 = a0;                      // pair 1

        for (int m = m0; m < m1; m++) {
            const float4* wm = wp + m * 147;
            int ch = g * 15 + m;
            const float2* q0 = s_pool + ch * POOL_CH_F2
                                      + (2 * i) * POOL_ROW_F2;
            const float2* q1 = q0 + 45 * POOL_CH_F2;
            #pragma unroll
            for (int j = 0; j < 7; j++) {
                float4 w = wm[j];
                float2 wx = make_float2(w.x, w.x);
                float2 wy = make_float2(w.y, w.y);
                float2 wz = make_float2(w.z, w.z);
                float2 ww = make_float2(w.w, w.w);
                a0 = ffma2(q0[2*j],                wx, a0);
                a0 = ffma2(q0[2*j + 1],            wy, a0);
                a1 = ffma2(q0[2*j + POOL_ROW_F2],  wz, a1);
                a1 = ffma2(q0[2*j + POOL_ROW_F2+1],ww, a1);
                c0 = ffma2(q1[2*j],                wx, c0);
                c0 = ffma2(q1[2*j + 1],            wy, c0);
                c1 = ffma2(q1[2*j + POOL_ROW_F2],  wz, c1);
                c1 = ffma2(q1[2*j + POOL_ROW_F2+1],ww, c1);
            }
        }

        float r0x = a0.x + a1.x, r0y = a0.y + a1.y;   // pair0 imgs 0/1
        float r1x = c0.x + c1.x, r1y = c0.y + c1.y;   // pair1 imgs 2/3
        r0x += __shfl_xor_sync(0xffffffffu, r0x, 1);
        r0y += __shfl_xor_sync(0xffffffffu, r0y, 1);
        r1x += __shfl_xor_sync(0xffffffffu, r1x, 1);
        r1y += __shfl_xor_sync(0xffffffffu, r1y, 1);

        if (mh == 0) {
            int idx = f * 21 + gi;                    // matches tree_b / FC order
            float tb = tree_b[idx];
            s_t[            idx] = sigmoidf_fast(r0x + tb);
            s_t[  336 +     idx] = sigmoidf_fast(r0y + tb);
            s_t[2*336 +     idx] = sigmoidf_fast(r1x + tb);
            s_t[3*336 +     idx] = sigmoidf_fast(r1y + tb);
        }
    }
    __syncthreads();

    // ---- phase 3: FC 336 -> 10 ----
    if (tid < 320) {
        int part  = tid & 7;
        int combo = tid >> 3;
        int img   = combo / 10;
        int o     = combo % 10;
        const float* tv = s_t + img * 336;
        const float* wv = fc_w + o * 336;
        float s = 0.f;
        for (int k = part; k < 336; k += 8)
            s = fmaf(tv[k], wv[k], s);
        s += __shfl_xor_sync(0xffffffffu, s, 1);
        s += __shfl_xor_sync(0xffffffffu, s, 2);
        s += __shfl_xor_sync(0xffffffffu, s, 4);
        if (part == 0)
            out[(b0 + img) * 10 + o] = s + fc_b[o];
    }
}

extern "C" void kernel_launch(void* const* d_in, const int* in_sizes, int n_in,
                              void* d_out, int out_size)
{
    const float* x      = (const float*)d_in[0];
    const float* conv_w = (const float*)d_in[1];
    const float* conv_b = (const float*)d_in[2];
    const float* tree_w = (const float*)d_in[3];
    const float* tree_b = (const float*)d_in[4];
    const float* fc_w   = (const float*)d_in[5];
    const float* fc_b   = (const float*)d_in[6];
    float* out = (float*)d_out;

    const int smem_bytes = SMEM_FLOATS * (int)sizeof(float);
    cudaFuncSetAttribute(tree3_fused,
                         cudaFuncAttributeMaxDynamicSharedMemorySize, smem_bytes);

    tree3_fused<<<BTOT / (2 * NPAIR), THREADS, smem_bytes>>>(
        x, conv_w, conv_b, tree_w, tree_b, fc_w, fc_b, out);
}